// round 3
// baseline (speedup 1.0000x reference)
#include <cuda_runtime.h>
#include <cstddef>
#include <cstdint>
#include <math.h>

#define SEQ   512
#define BATCH 256
#define INP   256
#define HID   512

typedef unsigned long long u64;

// ---------- packed f32x2 helpers (sm_103a) ----------
__device__ __forceinline__ u64 dup2(float x) {
    u64 r; asm("mov.b64 %0,{%1,%1};" : "=l"(r) : "f"(x)); return r;
}
__device__ __forceinline__ void fma2(u64& d, u64 a, u64 b) {
    asm("fma.rn.f32x2 %0,%1,%2,%0;" : "+l"(d) : "l"(a), "l"(b));
}
__device__ __forceinline__ void add2(u64& d, u64 a) {
    asm("add.rn.f32x2 %0,%0,%1;" : "+l"(d) : "l"(a));
}
__device__ __forceinline__ float2 upk(u64 v) {
    float2 f; asm("mov.b64 {%0,%1},%2;" : "=f"(f.x), "=f"(f.y) : "l"(v)); return f;
}

// ---------- scratch ----------
__device__ float g_xp[(size_t)SEQ * BATCH * 3 * HID];
__device__ float g_h[2][BATCH * HID];
__device__ unsigned          g_cnt[8 * 32];
__device__ volatile unsigned g_gen[8 * 32];

// ============================================================================
// Projection GEMM (unchanged): XP = X @ U^T + b for 3 weight sets.
// ============================================================================
__global__ void __launch_bounds__(256) proj_kernel(
    const float* __restrict__ X,
    const float* __restrict__ Uc, const float* __restrict__ bc,
    const float* __restrict__ Ua, const float* __restrict__ ba,
    const float* __restrict__ Uh, const float* __restrict__ bh)
{
    __shared__ __align__(16) float As[16][128];
    __shared__ __align__(16) float Bs[16][128];

    const int nt = blockIdx.x;
    const int mt = blockIdx.y;
    const int n0 = nt * 128, m0 = mt * 128;
    const int region = n0 >> 9;
    const float* __restrict__ U    = (region == 0) ? Uc : (region == 1 ? Ua : Uh);
    const float* __restrict__ bias = (region == 0) ? bc : (region == 1 ? ba : bh);
    const int nl0 = n0 & 511;

    const int tid = threadIdx.x;
    const int tn = tid & 15;
    const int tm = tid >> 4;
    const int lr = tid & 127;
    const int lc = tid >> 7;

    u64 acc[8][4];
    #pragma unroll
    for (int i = 0; i < 8; i++)
        #pragma unroll
        for (int q = 0; q < 4; q++) acc[i][q] = 0ull;

    for (int kt = 0; kt < 16; kt++) {
        const int k0 = kt * 16;
        #pragma unroll
        for (int half = 0; half < 2; half++) {
            int c = lc + 2 * half;
            float4 v = *(const float4*)&X[(size_t)(m0 + lr) * INP + k0 + c * 4];
            As[c * 4 + 0][lr] = v.x; As[c * 4 + 1][lr] = v.y;
            As[c * 4 + 2][lr] = v.z; As[c * 4 + 3][lr] = v.w;
        }
        #pragma unroll
        for (int half = 0; half < 2; half++) {
            int c = lc + 2 * half;
            float4 v = *(const float4*)&U[(size_t)(nl0 + lr) * INP + k0 + c * 4];
            Bs[c * 4 + 0][lr] = v.x; Bs[c * 4 + 1][lr] = v.y;
            Bs[c * 4 + 2][lr] = v.z; Bs[c * 4 + 3][lr] = v.w;
        }
        __syncthreads();

        #pragma unroll
        for (int k = 0; k < 16; k++) {
            float4 a0 = *(const float4*)&As[k][tm * 8];
            float4 a1 = *(const float4*)&As[k][tm * 8 + 4];
            ulonglong2 b0 = *(const ulonglong2*)&Bs[k][tn * 8];
            ulonglong2 b1 = *(const ulonglong2*)&Bs[k][tn * 8 + 4];
            u64 ad[8];
            ad[0] = dup2(a0.x); ad[1] = dup2(a0.y); ad[2] = dup2(a0.z); ad[3] = dup2(a0.w);
            ad[4] = dup2(a1.x); ad[5] = dup2(a1.y); ad[6] = dup2(a1.z); ad[7] = dup2(a1.w);
            #pragma unroll
            for (int i = 0; i < 8; i++) {
                fma2(acc[i][0], ad[i], b0.x);
                fma2(acc[i][1], ad[i], b0.y);
                fma2(acc[i][2], ad[i], b1.x);
                fma2(acc[i][3], ad[i], b1.y);
            }
        }
        __syncthreads();
    }

    float bv[8];
    #pragma unroll
    for (int q = 0; q < 8; q++) bv[q] = bias[nl0 + tn * 8 + q];
    #pragma unroll
    for (int i = 0; i < 8; i++) {
        const size_t m = (size_t)m0 + tm * 8 + i;
        float2 p0 = upk(acc[i][0]), p1 = upk(acc[i][1]);
        float2 p2 = upk(acc[i][2]), p3 = upk(acc[i][3]);
        float4 o0 = make_float4(p0.x + bv[0], p0.y + bv[1], p1.x + bv[2], p1.y + bv[3]);
        float4 o1 = make_float4(p2.x + bv[4], p2.y + bv[5], p3.x + bv[6], p3.y + bv[7]);
        float* dst = &g_xp[m * 1536 + n0 + tn * 8];
        *(float4*)dst       = o0;
        *(float4*)(dst + 4) = o1;
    }
}

// ============================================================================
// Recurrence v3: warp = full 32b x 32j tile over a 64-k slice (k-split x8),
// thread register-blocks 4b x 8j. Tree reduction over k-partials in SMEM.
// ============================================================================
#define HSTR 516

// Red float index for (chunk c, source-warp slot ws, lane)
#define RIDX(c, ws, lane) ((((c) * 4 + (ws)) * 32 + (lane)) * 4)

__global__ void __launch_bounds__(256, 1) recur_kernel(
    const float* __restrict__ h_in,
    const float* __restrict__ Wc, const float* __restrict__ Wa,
    float* __restrict__ out)
{
    extern __shared__ float sm[];
    float* Ws  = sm;                     // [512 k][64] : [k][j]=Wc, [k][32+j]=Wa (32768 f)
    float* Hs  = sm + 32768;             // [32 b][HSTR]                        (16512 f)
    float* Red = sm + 32768 + 16512;     // reduction buffer                    (8192 f)
    float* F   = Red + 4096;             // final hc/ha [2][32b][32j] (aliases Red)

    const int ct = blockIdx.x;           // 0..127
    const int jt = ct & 15, bt = ct >> 4;
    const int j0 = jt * 32, b0 = bt * 32;
    const int tid = threadIdx.x;
    const int w = tid >> 5, lane = tid & 31;
    const int jg = lane >> 3;            // j-group: 8 j
    const int bl = lane & 7;             // b-lane : b = bl + 8i
    const int kw0 = w * 64;              // this warp's k-slice

    // ---- stage weights into k-major SMEM (one-time) ----
    {
        const int j = lane;              // 0..31 (dense STS, strided LDG: one-time cost)
        for (int kc = w; kc < 128; kc += 8) {
            float4 wc = *(const float4*)&Wc[(size_t)(j0 + j) * HID + kc * 4];
            float4 wa = *(const float4*)&Wa[(size_t)(j0 + j) * HID + kc * 4];
            Ws[(kc * 4 + 0) * 64 + j] = wc.x; Ws[(kc * 4 + 1) * 64 + j] = wc.y;
            Ws[(kc * 4 + 2) * 64 + j] = wc.z; Ws[(kc * 4 + 3) * 64 + j] = wc.w;
            Ws[(kc * 4 + 0) * 64 + 32 + j] = wa.x; Ws[(kc * 4 + 1) * 64 + 32 + j] = wa.y;
            Ws[(kc * 4 + 2) * 64 + 32 + j] = wa.z; Ws[(kc * 4 + 3) * 64 + 32 + j] = wa.w;
        }
    }

    unsigned*          cnt = &g_cnt[bt * 32];
    volatile unsigned* gen = &g_gen[bt * 32];

    const int eb = tid >> 3;             // epilogue: b-row (0..31)
    const int ej = (tid & 7) * 4;        // epilogue: 4 local j

    for (int t = 0; t < SEQ; t++) {
        // prefetch this thread's input projections (long-latency LDG first)
        const size_t erow = (size_t)t * BATCH + b0 + eb;
        const float* __restrict__ xpp = &g_xp[erow * 1536];
        float4 xc = *(const float4*)&xpp[j0 + ej];
        float4 xa = *(const float4*)&xpp[512 + j0 + ej];
        float4 xh = *(const float4*)&xpp[1024 + j0 + ej];

        // stage h tile
        const float* __restrict__ hsrc = (t == 0) ? h_in : g_h[t & 1];
        for (int i = tid; i < 32 * 128; i += 256) {
            int r = i >> 7, c = (i & 127) << 2;
            *(float4*)&Hs[r * HSTR + c] =
                *(const float4*)&hsrc[(size_t)(b0 + r) * HID + c];
        }
        __syncthreads();

        // ---- matvec over this warp's 64-k slice ----
        u64 acc[2][4][4];
        #pragma unroll
        for (int m = 0; m < 2; m++)
            #pragma unroll
            for (int i = 0; i < 4; i++)
                #pragma unroll
                for (int p = 0; p < 4; p++) acc[m][i][p] = 0ull;

        #pragma unroll 2
        for (int k4 = 0; k4 < 16; k4++) {
            const int kk = kw0 + k4 * 4;
            float4 hv[4];
            #pragma unroll
            for (int i = 0; i < 4; i++)
                hv[i] = *(const float4*)&Hs[(bl + 8 * i) * HSTR + kk];
            #pragma unroll
            for (int q = 0; q < 4; q++) {
                const float* wr = &Ws[(kk + q) * 64];
                ulonglong2 c0 = *(const ulonglong2*)&wr[jg * 8];
                ulonglong2 c1 = *(const ulonglong2*)&wr[jg * 8 + 4];
                ulonglong2 a0 = *(const ulonglong2*)&wr[32 + jg * 8];
                ulonglong2 a1 = *(const ulonglong2*)&wr[32 + jg * 8 + 4];
                #pragma unroll
                for (int i = 0; i < 4; i++) {
                    float hq = (q == 0) ? hv[i].x : (q == 1) ? hv[i].y
                             : (q == 2) ? hv[i].z : hv[i].w;
                    u64 hd = dup2(hq);
                    fma2(acc[0][i][0], hd, c0.x); fma2(acc[0][i][1], hd, c0.y);
                    fma2(acc[0][i][2], hd, c1.x); fma2(acc[0][i][3], hd, c1.y);
                    fma2(acc[1][i][0], hd, a0.x); fma2(acc[1][i][1], hd, a0.y);
                    fma2(acc[1][i][2], hd, a1.x); fma2(acc[1][i][3], hd, a1.y);
                }
            }
        }

        // ---- tree reduction of k-partials: 8 -> 4 -> 2 -> 1 (warp 0) ----
        #define RED_STORE(WS)                                                      \
            { _Pragma("unroll")                                                    \
              for (int m = 0; m < 2; m++) _Pragma("unroll")                        \
              for (int i = 0; i < 4; i++) _Pragma("unroll")                        \
              for (int hh = 0; hh < 2; hh++) {                                     \
                  int c = (m * 4 + i) * 2 + hh;                                    \
                  *(ulonglong2*)&Red[RIDX(c, (WS), lane)] =                        \
                      make_ulonglong2(acc[m][i][2 * hh], acc[m][i][2 * hh + 1]);   \
              } }
        #define RED_ADD(WS)                                                        \
            { _Pragma("unroll")                                                    \
              for (int m = 0; m < 2; m++) _Pragma("unroll")                        \
              for (int i = 0; i < 4; i++) _Pragma("unroll")                        \
              for (int hh = 0; hh < 2; hh++) {                                     \
                  int c = (m * 4 + i) * 2 + hh;                                    \
                  ulonglong2 v = *(const ulonglong2*)&Red[RIDX(c, (WS), lane)];    \
                  add2(acc[m][i][2 * hh], v.x); add2(acc[m][i][2 * hh + 1], v.y);  \
              } }

        if (w >= 4) RED_STORE(w - 4)
        __syncthreads();
        if (w < 4) RED_ADD(w)
        __syncthreads();
        if (w == 2 || w == 3) RED_STORE(w - 2)
        __syncthreads();
        if (w < 2) RED_ADD(w)
        __syncthreads();
        if (w == 1) RED_STORE(0)
        __syncthreads();
        if (w == 0) {
            RED_ADD(0)
            __syncwarp();
            // write final hc/ha: F[m][b][j]
            #pragma unroll
            for (int m = 0; m < 2; m++)
                #pragma unroll
                for (int i = 0; i < 4; i++)
                    #pragma unroll
                    for (int hh = 0; hh < 2; hh++)
                        *(ulonglong2*)&F[m * 1024 + (bl + 8 * i) * 32 + jg * 8 + hh * 4] =
                            make_ulonglong2(acc[m][i][2 * hh], acc[m][i][2 * hh + 1]);
        }
        __syncthreads();

        // ---- gated elementwise update (distributed over all 256 threads) ----
        {
            float4 hc4 = *(const float4*)&F[eb * 32 + ej];
            float4 ha4 = *(const float4*)&F[1024 + eb * 32 + ej];
            float4 hp4 = *(const float4*)&Hs[eb * HSTR + j0 + ej];
            float hcv[4] = {hc4.x, hc4.y, hc4.z, hc4.w};
            float hav[4] = {ha4.x, ha4.y, ha4.z, ha4.w};
            float hps[4] = {hp4.x, hp4.y, hp4.z, hp4.w};
            float xcv[4] = {xc.x, xc.y, xc.z, xc.w};
            float xav[4] = {xa.x, xa.y, xa.z, xa.w};
            float xhv[4] = {xh.x, xh.y, xh.z, xh.w};
            float rr[4];
            #pragma unroll
            for (int q = 0; q < 4; q++) {
                float cg = 1.0f / (1.0f + expf(-(xcv[q] + hcv[q])));
                float ag = 1.0f + tanhf(xav[q] + hav[q]);
                rr[q] = cg * hps[q] + (1.0f - cg) * tanhf(xhv[q] + ag * hps[q]);
            }
            float4 r4 = make_float4(rr[0], rr[1], rr[2], rr[3]);
            *(float4*)&out[erow * HID + j0 + ej] = r4;
            *(float4*)&g_h[(t + 1) & 1][(size_t)(b0 + eb) * HID + j0 + ej] = r4;
            if (t == SEQ - 1)
                *(float4*)&out[(size_t)SEQ * BATCH * HID +
                               (size_t)(b0 + eb) * HID + j0 + ej] = r4;
        }

        // ---- 16-way inter-CTA barrier per batch tile ----
        if (t < SEQ - 1) {
            __threadfence();
            __syncthreads();
            if (tid == 0) {
                unsigned g = *gen;
                if (atomicAdd(cnt, 1u) == 15u) {
                    atomicExch(cnt, 0u);
                    __threadfence();
                    *gen = g + 1;
                } else {
                    while (*gen == g) __nanosleep(40);
                    __threadfence();
                }
            }
            __syncthreads();
        }
    }
}

// ============================================================================
extern "C" void kernel_launch(void* const* d_in, const int* in_sizes, int n_in,
                              void* d_out, int out_size)
{
    const float* X  = (const float*)d_in[0];
    const float* h0 = (const float*)d_in[1];
    const float* Uc = (const float*)d_in[2];
    const float* Wc = (const float*)d_in[3];
    const float* bc = (const float*)d_in[4];
    const float* Ua = (const float*)d_in[5];
    const float* Wa = (const float*)d_in[6];
    const float* ba = (const float*)d_in[7];
    const float* Uh = (const float*)d_in[8];
    const float* bh = (const float*)d_in[9];
    float* out = (float*)d_out;

    const size_t shmem = (size_t)(32768 + 16512 + 8192) * sizeof(float); // 229888 B
    cudaFuncSetAttribute(recur_kernel, cudaFuncAttributeMaxDynamicSharedMemorySize,
                         (int)shmem);

    dim3 pg(12, 1024);
    proj_kernel<<<pg, 256>>>(X, Uc, bc, Ua, ba, Uh, bh);
    recur_kernel<<<128, 256, shmem>>>(h0, Wc, Wa, out);
}

// round 4
// speedup vs baseline: 1.6787x; 1.6787x over previous
#include <cuda_runtime.h>
#include <cstddef>
#include <cstdint>
#include <math.h>

#define SEQ   512
#define BATCH 256
#define INP   256
#define HID   512

typedef unsigned long long u64;

// ---------- packed f32x2 helpers (sm_103a) ----------
__device__ __forceinline__ u64 dup2(float x) {
    u64 r; asm("mov.b64 %0,{%1,%1};" : "=l"(r) : "f"(x)); return r;
}
__device__ __forceinline__ void fma2(u64& d, u64 a, u64 b) {
    asm("fma.rn.f32x2 %0,%1,%2,%0;" : "+l"(d) : "l"(a), "l"(b));
}
__device__ __forceinline__ void add2(u64& d, u64 a) {
    asm("add.rn.f32x2 %0,%0,%1;" : "+l"(d) : "l"(a));
}
__device__ __forceinline__ float2 upk(u64 v) {
    float2 f; asm("mov.b64 {%0,%1},%2;" : "=f"(f.x), "=f"(f.y) : "l"(v)); return f;
}

// ---------- sync helpers ----------
__device__ __forceinline__ unsigned ld_acq(const unsigned* p) {
    unsigned v;
    asm volatile("ld.acquire.gpu.global.b32 %0,[%1];" : "=r"(v) : "l"(p) : "memory");
    return v;
}
__device__ __forceinline__ void st_rel(unsigned* p, unsigned v) {
    asm volatile("st.release.gpu.global.b32 [%0],%1;" :: "l"(p), "r"(v) : "memory");
}

// ---------- fast activations (error ~1e-6, tol 1e-3) ----------
__device__ __forceinline__ float sig_f(float z) {
    return __fdividef(1.0f, 1.0f + __expf(-z));
}
__device__ __forceinline__ float tanh_f(float z) {
    return 1.0f - __fdividef(2.0f, __expf(2.0f * z) + 1.0f);
}

// ---------- scratch ----------
__device__ float g_xp[(size_t)SEQ * BATCH * 3 * HID];
__device__ float g_h[2][BATCH * HID];
__device__ unsigned g_cnt[8 * 32];
__device__ unsigned g_gen[8 * 32];

// ============================================================================
// Projection GEMM (unchanged): XP = X @ U^T + b for 3 weight sets.
// ============================================================================
__global__ void __launch_bounds__(256) proj_kernel(
    const float* __restrict__ X,
    const float* __restrict__ Uc, const float* __restrict__ bc,
    const float* __restrict__ Ua, const float* __restrict__ ba,
    const float* __restrict__ Uh, const float* __restrict__ bh)
{
    __shared__ __align__(16) float As[16][128];
    __shared__ __align__(16) float Bs[16][128];

    const int nt = blockIdx.x;
    const int mt = blockIdx.y;
    const int n0 = nt * 128, m0 = mt * 128;
    const int region = n0 >> 9;
    const float* __restrict__ U    = (region == 0) ? Uc : (region == 1 ? Ua : Uh);
    const float* __restrict__ bias = (region == 0) ? bc : (region == 1 ? ba : bh);
    const int nl0 = n0 & 511;

    const int tid = threadIdx.x;
    const int tn = tid & 15;
    const int tm = tid >> 4;
    const int lr = tid & 127;
    const int lc = tid >> 7;

    u64 acc[8][4];
    #pragma unroll
    for (int i = 0; i < 8; i++)
        #pragma unroll
        for (int q = 0; q < 4; q++) acc[i][q] = 0ull;

    for (int kt = 0; kt < 16; kt++) {
        const int k0 = kt * 16;
        #pragma unroll
        for (int half = 0; half < 2; half++) {
            int c = lc + 2 * half;
            float4 v = *(const float4*)&X[(size_t)(m0 + lr) * INP + k0 + c * 4];
            As[c * 4 + 0][lr] = v.x; As[c * 4 + 1][lr] = v.y;
            As[c * 4 + 2][lr] = v.z; As[c * 4 + 3][lr] = v.w;
        }
        #pragma unroll
        for (int half = 0; half < 2; half++) {
            int c = lc + 2 * half;
            float4 v = *(const float4*)&U[(size_t)(nl0 + lr) * INP + k0 + c * 4];
            Bs[c * 4 + 0][lr] = v.x; Bs[c * 4 + 1][lr] = v.y;
            Bs[c * 4 + 2][lr] = v.z; Bs[c * 4 + 3][lr] = v.w;
        }
        __syncthreads();

        #pragma unroll
        for (int k = 0; k < 16; k++) {
            float4 a0 = *(const float4*)&As[k][tm * 8];
            float4 a1 = *(const float4*)&As[k][tm * 8 + 4];
            ulonglong2 b0 = *(const ulonglong2*)&Bs[k][tn * 8];
            ulonglong2 b1 = *(const ulonglong2*)&Bs[k][tn * 8 + 4];
            u64 ad[8];
            ad[0] = dup2(a0.x); ad[1] = dup2(a0.y); ad[2] = dup2(a0.z); ad[3] = dup2(a0.w);
            ad[4] = dup2(a1.x); ad[5] = dup2(a1.y); ad[6] = dup2(a1.z); ad[7] = dup2(a1.w);
            #pragma unroll
            for (int i = 0; i < 8; i++) {
                fma2(acc[i][0], ad[i], b0.x);
                fma2(acc[i][1], ad[i], b0.y);
                fma2(acc[i][2], ad[i], b1.x);
                fma2(acc[i][3], ad[i], b1.y);
            }
        }
        __syncthreads();
    }

    float bv[8];
    #pragma unroll
    for (int q = 0; q < 8; q++) bv[q] = bias[nl0 + tn * 8 + q];
    #pragma unroll
    for (int i = 0; i < 8; i++) {
        const size_t m = (size_t)m0 + tm * 8 + i;
        float2 p0 = upk(acc[i][0]), p1 = upk(acc[i][1]);
        float2 p2 = upk(acc[i][2]), p3 = upk(acc[i][3]);
        float4 o0 = make_float4(p0.x + bv[0], p0.y + bv[1], p1.x + bv[2], p1.y + bv[3]);
        float4 o1 = make_float4(p2.x + bv[4], p2.y + bv[5], p3.x + bv[6], p3.y + bv[7]);
        float* dst = &g_xp[m * 1536 + n0 + tn * 8];
        *(float4*)dst       = o0;
        *(float4*)(dst + 4) = o1;
    }
}

// ============================================================================
// Recurrence v4: 512 threads. Warp = (kslice in 8) x (jhalf in 2).
// Warp tile 16j x 32b x 64k; thread 4j x 4b. Weights read once per step.
// Flat 2-round partial reduction (32KB), fused consumer epilogue.
// Lean replay-safe inter-CTA barrier (acquire poll, release signal).
// ============================================================================
#define HSTR 516

__global__ void __launch_bounds__(512, 1) recur_kernel(
    const float* __restrict__ h_in,
    const float* __restrict__ Wc, const float* __restrict__ Wa,
    float* __restrict__ out)
{
    extern __shared__ float sm[];
    float* Ws  = sm;                     // [512k][64]: [k][j]=Wc, [k][32+j]=Wa (32768 f)
    float* Hs  = sm + 32768;             // [32 b][HSTR]                       (16512 f)
    float* Red = sm + 32768 + 16512;     // partials, 2048 x 16B chunks        ( 8192 f)
    ulonglong2* RedU = (ulonglong2*)Red;

    const int ct = blockIdx.x;           // 0..127
    const int jt = ct & 15, bt = ct >> 4;
    const int j0 = jt * 32, b0 = bt * 32;
    const int tid = threadIdx.x;
    const int w = tid >> 5, lane = tid & 31;
    const int ks = w >> 1, jh = w & 1;   // k-slice (8), j-half (2)
    const int jg = lane >> 3;            // j-group within half (4 of 4j)
    const int bl = lane & 7;             // b-lane: b = bl + 8i
    const int kw0 = ks * 64;
    const int jwl = jh * 16 + jg * 4;    // local j base (producer)

    // consumer mapping: tid = b*16 + jp, j = jp*2 (+0,+1)
    const int cb  = tid >> 4;
    const int jp  = tid & 15;
    const int cjh = jp >> 3;
    const int cjg = (jp >> 1) & 3;
    const int cje = (jp & 1) * 2;
    const int ci  = cb >> 3, cbl = cb & 7;
    // float base into Red for (mat=0, ksm=0); mat offset 512 f, ksm stride 2048 f
    const int rbase = (((cjh * 8 + ci) * 32 + cbl * 4 + cjg) << 2) + cje;

    // producer chunk base (ulonglong2 index), n = mat*4+i offset is *32
    const int ksm = ks & 3;
    const int pbase = ((ksm * 2 + jh) * 8) * 32 + bl * 4 + jg;

    // ---- stage weights (one-time) ----
    for (int idx = tid; idx < 32 * 128; idx += 512) {
        int j = idx >> 7, k = (idx & 127) << 2;
        float4 wc = __ldcg((const float4*)&Wc[(size_t)(j0 + j) * HID + k]);
        float4 wa = __ldcg((const float4*)&Wa[(size_t)(j0 + j) * HID + k]);
        Ws[(k + 0) * 64 + j] = wc.x; Ws[(k + 1) * 64 + j] = wc.y;
        Ws[(k + 2) * 64 + j] = wc.z; Ws[(k + 3) * 64 + j] = wc.w;
        Ws[(k + 0) * 64 + 32 + j] = wa.x; Ws[(k + 1) * 64 + 32 + j] = wa.y;
        Ws[(k + 2) * 64 + 32 + j] = wa.z; Ws[(k + 3) * 64 + 32 + j] = wa.w;
    }

    unsigned* cnt = &g_cnt[bt * 32];
    unsigned* gen = &g_gen[bt * 32];
    __shared__ unsigned s_g0;
    if (tid == 0) s_g0 = *gen;           // replay-safe generation base
    __syncthreads();
    const unsigned g0 = s_g0;

    for (int t = 0; t < SEQ; t++) {
        // prefetch input projections (consumer-mapped, streamed via L2)
        const size_t crow = (size_t)t * BATCH + b0 + cb;
        const float* xpb = &g_xp[crow * 1536 + j0 + jp * 2];
        float2 xc = __ldcg((const float2*)(xpb));
        float2 xa = __ldcg((const float2*)(xpb + 512));
        float2 xh = __ldcg((const float2*)(xpb + 1024));

        // stage h tile (L2 reads: g_h written by other SMs)
        const float* __restrict__ hsrc = (t == 0) ? h_in : g_h[t & 1];
        for (int i = tid; i < 32 * 128; i += 512) {
            int r = i >> 7, c = (i & 127) << 2;
            *(float4*)&Hs[r * HSTR + c] =
                __ldcg((const float4*)&hsrc[(size_t)(b0 + r) * HID + c]);
        }
        __syncthreads();

        // ---- matvec over this warp's 64-k slice, 16j x 32b ----
        u64 acc[2][4][2];
        #pragma unroll
        for (int m = 0; m < 2; m++)
            #pragma unroll
            for (int i = 0; i < 4; i++) { acc[m][i][0] = 0ull; acc[m][i][1] = 0ull; }

        #pragma unroll 2
        for (int k4 = 0; k4 < 16; k4++) {
            const int kk = kw0 + k4 * 4;
            float4 hv[4];
            #pragma unroll
            for (int i = 0; i < 4; i++)
                hv[i] = *(const float4*)&Hs[(bl + 8 * i) * HSTR + kk];
            #pragma unroll
            for (int q = 0; q < 4; q++) {
                const float* wr = &Ws[(kk + q) * 64 + jwl];
                ulonglong2 wc = *(const ulonglong2*)wr;
                ulonglong2 wa = *(const ulonglong2*)(wr + 32);
                #pragma unroll
                for (int i = 0; i < 4; i++) {
                    float hq = (q == 0) ? hv[i].x : (q == 1) ? hv[i].y
                             : (q == 2) ? hv[i].z : hv[i].w;
                    u64 hd = dup2(hq);
                    fma2(acc[0][i][0], hd, wc.x); fma2(acc[0][i][1], hd, wc.y);
                    fma2(acc[1][i][0], hd, wa.x); fma2(acc[1][i][1], hd, wa.y);
                }
            }
        }

        // ---- round 1: k-slices 0-3 store partials (conflict-free chunks) ----
        if (ks < 4) {
            #pragma unroll
            for (int m = 0; m < 2; m++)
                #pragma unroll
                for (int i = 0; i < 4; i++)
                    RedU[pbase + (m * 4 + i) * 32] =
                        make_ulonglong2(acc[m][i][0], acc[m][i][1]);
        }
        __syncthreads();
        // ---- round 2: k-slices 4-7 accumulate in place ----
        if (ks >= 4) {
            #pragma unroll
            for (int m = 0; m < 2; m++)
                #pragma unroll
                for (int i = 0; i < 4; i++) {
                    const int idx = pbase + (m * 4 + i) * 32;
                    ulonglong2 v = RedU[idx];
                    add2(acc[m][i][0], v.x); add2(acc[m][i][1], v.y);
                    RedU[idx] = make_ulonglong2(acc[m][i][0], acc[m][i][1]);
                }
        }
        __syncthreads();

        // ---- consumer: sum 4 regions, fused gated epilogue, stores ----
        {
            float2 hc = make_float2(0.f, 0.f), ha = make_float2(0.f, 0.f);
            #pragma unroll
            for (int r = 0; r < 4; r++) {
                float2 vc = *(const float2*)&Red[rbase + r * 2048];
                float2 va = *(const float2*)&Red[rbase + r * 2048 + 512];
                hc.x += vc.x; hc.y += vc.y;
                ha.x += va.x; ha.y += va.y;
            }
            float2 hp = *(const float2*)&Hs[cb * HSTR + j0 + jp * 2];

            float r0, r1;
            {
                float cg = sig_f(xc.x + hc.x);
                float ag = 1.0f + tanh_f(xa.x + ha.x);
                r0 = cg * hp.x + (1.0f - cg) * tanh_f(xh.x + ag * hp.x);
            }
            {
                float cg = sig_f(xc.y + hc.y);
                float ag = 1.0f + tanh_f(xa.y + ha.y);
                r1 = cg * hp.y + (1.0f - cg) * tanh_f(xh.y + ag * hp.y);
            }
            float2 rv = make_float2(r0, r1);
            *(float2*)&out[crow * HID + j0 + jp * 2] = rv;
            *(float2*)&g_h[(t + 1) & 1][(size_t)(b0 + cb) * HID + j0 + jp * 2] = rv;
            if (t == SEQ - 1)
                *(float2*)&out[(size_t)SEQ * BATCH * HID +
                               (size_t)(b0 + cb) * HID + j0 + jp * 2] = rv;
        }

        // ---- lean 16-way inter-CTA barrier (per batch tile) ----
        if (t < SEQ - 1) {
            __syncthreads();
            if (tid == 0) {
                __threadfence();
                const unsigned target = g0 + (unsigned)t + 1u;
                if (atomicAdd(cnt, 1u) == 15u) {
                    atomicExch(cnt, 0u);
                    __threadfence();
                    st_rel(gen, target);
                } else {
                    while (ld_acq(gen) != target) { }
                }
            }
            __syncthreads();
        }
    }
}

// ============================================================================
extern "C" void kernel_launch(void* const* d_in, const int* in_sizes, int n_in,
                              void* d_out, int out_size)
{
    const float* X  = (const float*)d_in[0];
    const float* h0 = (const float*)d_in[1];
    const float* Uc = (const float*)d_in[2];
    const float* Wc = (const float*)d_in[3];
    const float* bc = (const float*)d_in[4];
    const float* Ua = (const float*)d_in[5];
    const float* Wa = (const float*)d_in[6];
    const float* ba = (const float*)d_in[7];
    const float* Uh = (const float*)d_in[8];
    const float* bh = (const float*)d_in[9];
    float* out = (float*)d_out;

    const size_t shmem = (size_t)(32768 + 16512 + 8192) * sizeof(float); // 229888 B
    cudaFuncSetAttribute(recur_kernel, cudaFuncAttributeMaxDynamicSharedMemorySize,
                         (int)shmem);

    dim3 pg(12, 1024);
    proj_kernel<<<pg, 256>>>(X, Uc, bc, Ua, ba, Uh, bh);
    recur_kernel<<<128, 512, shmem>>>(h0, Wc, Wa, out);
}